// round 1
// baseline (speedup 1.0000x reference)
#include <cuda_runtime.h>
#include <math.h>

#define D_MODEL 512
#define NHEAD   8
#define DK      64
#define BATCH   8
#define SEQ     2048
#define BH      (BATCH * NHEAD)      // 64
#define MROWS   (BATCH * SEQ)        // 16384

// Scratch: head-split projected q/k/v and attention output, [BH][SEQ][DK]
__device__ float g_q[(size_t)BH * SEQ * DK];
__device__ float g_k[(size_t)BH * SEQ * DK];
__device__ float g_v[(size_t)BH * SEQ * DK];
__device__ float g_o[(size_t)BH * SEQ * DK];

// ---------------------------------------------------------------------------
// Projection GEMM: out = X @ W^T + b, written head-split into g_q/g_k/g_v.
// 64x64 tile, 256 threads, 4x4 microtile, K-chunk 32.
// ---------------------------------------------------------------------------
__global__ void proj_kernel(const float* __restrict__ X,
                            const float* __restrict__ W,
                            const float* __restrict__ bias,
                            int which)   // 0=q 1=k 2=v
{
    __shared__ float sX[64 * 33];
    __shared__ float sW[64 * 33];

    float* dst = (which == 0) ? g_q : (which == 1) ? g_k : g_v;

    const int bm = blockIdx.x * 64;
    const int bn = blockIdx.y * 64;
    const int t  = threadIdx.x;
    const int tx = t & 15;
    const int ty = t >> 4;

    float acc[4][4];
#pragma unroll
    for (int i = 0; i < 4; i++)
#pragma unroll
        for (int j = 0; j < 4; j++) acc[i][j] = 0.f;

    for (int kc = 0; kc < D_MODEL; kc += 32) {
#pragma unroll
        for (int i = t; i < 64 * 32; i += 256) {
            int r = i >> 5, c = i & 31;
            sX[r * 33 + c] = X[(size_t)(bm + r) * D_MODEL + kc + c];
            sW[r * 33 + c] = W[(size_t)(bn + r) * D_MODEL + kc + c];
        }
        __syncthreads();
#pragma unroll 8
        for (int kk = 0; kk < 32; kk++) {
            float a[4], b[4];
#pragma unroll
            for (int i = 0; i < 4; i++) a[i] = sX[(ty * 4 + i) * 33 + kk];
#pragma unroll
            for (int j = 0; j < 4; j++) b[j] = sW[(tx * 4 + j) * 33 + kk];
#pragma unroll
            for (int i = 0; i < 4; i++)
#pragma unroll
                for (int j = 0; j < 4; j++) acc[i][j] += a[i] * b[j];
        }
        __syncthreads();
    }

#pragma unroll
    for (int i = 0; i < 4; i++) {
        int m = bm + ty * 4 + i;
        int b = m >> 11;            // /SEQ
        int s = m & (SEQ - 1);
#pragma unroll
        for (int j = 0; j < 4; j++) {
            int n = bn + tx * 4 + j;
            float v = acc[i][j] + bias[n];
            int h = n >> 6, d = n & 63;
            dst[((size_t)(b * NHEAD + h) * SEQ + s) * DK + d] = v;
        }
    }
}

// ---------------------------------------------------------------------------
// Flash attention: one block = (head bh, 64 q-rows). Online softmax, all
// per-row state (m, l, alpha) in registers (score-row distribution == O-row
// distribution). K smem buffer is reused for the P tile.
// smem: sQ 64x64 | sK/P 64x65 | sV 64x64  = 49408 B (dynamic)
// ---------------------------------------------------------------------------
#define FLASH_SMEM ((64 * 64 + 64 * 65 + 64 * 64) * 4)

__global__ void flash_attn_kernel(const int* __restrict__ mask)
{
    extern __shared__ float sm[];
    float* sQ = sm;                       // [64][64]
    float* sK = sm + 64 * 64;             // [64][65]  (later P [64][65])
    float* sV = sK + 64 * 65;             // [64][64]

    const int bh = blockIdx.y;
    const int qt = blockIdx.x;
    const float* qp = g_q + ((size_t)bh * SEQ + qt * 64) * DK;
    const float* kp = g_k + (size_t)bh * SEQ * DK;
    const float* vp = g_v + (size_t)bh * SEQ * DK;

    const int t  = threadIdx.x;
    const int tx = t & 15;
    const int ty = t >> 4;

    // load Q tile (contiguous)
#pragma unroll
    for (int i = t; i < 64 * DK; i += 256) sQ[i] = qp[i];

    float m_i[4], l_i[4], acc[4][4];
#pragma unroll
    for (int i = 0; i < 4; i++) {
        m_i[i] = -INFINITY;
        l_i[i] = 0.f;
#pragma unroll
        for (int j = 0; j < 4; j++) acc[i][j] = 0.f;
    }
    __syncthreads();

    const int qg0 = qt * 64 + ty * 4;

    for (int kt = 0; kt < SEQ / 64; kt++) {
        const float* kpt = kp + (size_t)kt * 64 * DK;
        const float* vpt = vp + (size_t)kt * 64 * DK;
#pragma unroll
        for (int i = t; i < 64 * DK; i += 256) {
            int r = i >> 6, c = i & 63;
            sK[r * 65 + c] = kpt[i];
            sV[i]          = vpt[i];
        }
        __syncthreads();

        // S = Q K^T
        float s[4][4];
#pragma unroll
        for (int i = 0; i < 4; i++)
#pragma unroll
            for (int j = 0; j < 4; j++) s[i][j] = 0.f;
#pragma unroll 8
        for (int dd = 0; dd < DK; dd++) {
            float a[4], b[4];
#pragma unroll
            for (int i = 0; i < 4; i++) a[i] = sQ[(ty * 4 + i) * DK + dd];
#pragma unroll
            for (int j = 0; j < 4; j++) b[j] = sK[(tx * 4 + j) * 65 + dd];
#pragma unroll
            for (int i = 0; i < 4; i++)
#pragma unroll
                for (int j = 0; j < 4; j++) s[i][j] += a[i] * b[j];
        }

        // scale + mask
        const int kg0 = kt * 64 + tx * 4;
#pragma unroll
        for (int i = 0; i < 4; i++) {
            const int* mrow = mask + (size_t)(qg0 + i) * SEQ + kg0;
#pragma unroll
            for (int j = 0; j < 4; j++) {
                float v = s[i][j] * 0.125f;       // 1/sqrt(64)
                if (mrow[j] == 0) v = -1e30f;
                s[i][j] = v;
            }
        }

        // online softmax (row state replicated across the 16-lane tx group)
        float mnew[4], alpha[4], rowsum[4];
#pragma unroll
        for (int i = 0; i < 4; i++) {
            float r = fmaxf(fmaxf(s[i][0], s[i][1]), fmaxf(s[i][2], s[i][3]));
#pragma unroll
            for (int o = 8; o > 0; o >>= 1)
                r = fmaxf(r, __shfl_xor_sync(0xffffffffu, r, o));
            mnew[i]  = fmaxf(m_i[i], r);
            alpha[i] = __expf(m_i[i] - mnew[i]);
            m_i[i]   = mnew[i];
        }
#pragma unroll
        for (int i = 0; i < 4; i++) {
            float rs = 0.f;
#pragma unroll
            for (int j = 0; j < 4; j++) {
                s[i][j] = __expf(s[i][j] - mnew[i]);   // s becomes P
                rs += s[i][j];
            }
#pragma unroll
            for (int o = 8; o > 0; o >>= 1)
                rs += __shfl_xor_sync(0xffffffffu, rs, o);
            rowsum[i] = rs;
            l_i[i] = l_i[i] * alpha[i] + rowsum[i];
        }

        __syncthreads();          // all reads of sK done -> reuse as P
#pragma unroll
        for (int i = 0; i < 4; i++)
#pragma unroll
            for (int j = 0; j < 4; j++)
                sK[(ty * 4 + i) * 65 + tx * 4 + j] = s[i][j];
        __syncthreads();

        // O = O*alpha + P V
#pragma unroll
        for (int i = 0; i < 4; i++)
#pragma unroll
            for (int j = 0; j < 4; j++) acc[i][j] *= alpha[i];
#pragma unroll 8
        for (int n = 0; n < 64; n++) {
            float pv[4], vv[4];
#pragma unroll
            for (int i = 0; i < 4; i++) pv[i] = sK[(ty * 4 + i) * 65 + n];
#pragma unroll
            for (int j = 0; j < 4; j++) vv[j] = sV[n * DK + tx * 4 + j];
#pragma unroll
            for (int i = 0; i < 4; i++)
#pragma unroll
                for (int j = 0; j < 4; j++) acc[i][j] += pv[i] * vv[j];
        }
        __syncthreads();          // P/V reads done before next tile load
    }

    float* op = g_o + ((size_t)bh * SEQ + qt * 64) * DK;
#pragma unroll
    for (int i = 0; i < 4; i++) {
        float inv = 1.f / l_i[i];
#pragma unroll
        for (int j = 0; j < 4; j++)
            op[(size_t)(ty * 4 + i) * DK + tx * 4 + j] = acc[i][j] * inv;
    }
}

// ---------------------------------------------------------------------------
// Output projection: out = concat(heads) @ Wo^T + bo  (gathered read of g_o)
// ---------------------------------------------------------------------------
__global__ void out_proj_kernel(const float* __restrict__ Wo,
                                const float* __restrict__ bo,
                                float* __restrict__ out)
{
    __shared__ float sX[64 * 33];
    __shared__ float sW[64 * 33];

    const int bm = blockIdx.x * 64;
    const int bn = blockIdx.y * 64;
    const int t  = threadIdx.x;
    const int tx = t & 15;
    const int ty = t >> 4;

    float acc[4][4];
#pragma unroll
    for (int i = 0; i < 4; i++)
#pragma unroll
        for (int j = 0; j < 4; j++) acc[i][j] = 0.f;

    for (int kc = 0; kc < D_MODEL; kc += 32) {
#pragma unroll
        for (int i = t; i < 64 * 32; i += 256) {
            int r = i >> 5, c = i & 31;
            int m = bm + r;
            int b = m >> 11, s = m & (SEQ - 1);
            int ch = kc + c;
            int h = ch >> 6, d = ch & 63;
            sX[r * 33 + c] = g_o[((size_t)(b * NHEAD + h) * SEQ + s) * DK + d];
            sW[r * 33 + c] = Wo[(size_t)(bn + r) * D_MODEL + kc + c];
        }
        __syncthreads();
#pragma unroll 8
        for (int kk = 0; kk < 32; kk++) {
            float a[4], b[4];
#pragma unroll
            for (int i = 0; i < 4; i++) a[i] = sX[(ty * 4 + i) * 33 + kk];
#pragma unroll
            for (int j = 0; j < 4; j++) b[j] = sW[(tx * 4 + j) * 33 + kk];
#pragma unroll
            for (int i = 0; i < 4; i++)
#pragma unroll
                for (int j = 0; j < 4; j++) acc[i][j] += a[i] * b[j];
        }
        __syncthreads();
    }

#pragma unroll
    for (int i = 0; i < 4; i++) {
        int m = bm + ty * 4 + i;
#pragma unroll
        for (int j = 0; j < 4; j++) {
            int n = bn + tx * 4 + j;
            out[(size_t)m * D_MODEL + n] = acc[i][j] + bo[n];
        }
    }
}

// ---------------------------------------------------------------------------
extern "C" void kernel_launch(void* const* d_in, const int* in_sizes, int n_in,
                              void* d_out, int out_size)
{
    const float* Q    = (const float*)d_in[0];
    const float* K    = (const float*)d_in[1];
    const float* V    = (const float*)d_in[2];
    const int*   mask = (const int*)  d_in[3];
    const float* Wq   = (const float*)d_in[4];
    const float* bq   = (const float*)d_in[5];
    const float* Wk   = (const float*)d_in[6];
    const float* bk   = (const float*)d_in[7];
    const float* Wv   = (const float*)d_in[8];
    const float* bv   = (const float*)d_in[9];
    const float* Wo   = (const float*)d_in[10];
    const float* bo   = (const float*)d_in[11];
    float* out = (float*)d_out;

    cudaFuncSetAttribute(flash_attn_kernel,
                         cudaFuncAttributeMaxDynamicSharedMemorySize, FLASH_SMEM);

    dim3 pg(MROWS / 64, D_MODEL / 64);          // 256 x 8
    proj_kernel<<<pg, 256>>>(Q, Wq, bq, 0);
    proj_kernel<<<pg, 256>>>(K, Wk, bk, 1);
    proj_kernel<<<pg, 256>>>(V, Wv, bv, 2);

    dim3 ag(SEQ / 64, BH);                      // 32 x 64
    flash_attn_kernel<<<ag, 256, FLASH_SMEM>>>(mask);

    out_proj_kernel<<<pg, 256>>>(Wo, bo, out);
}

// round 2
// speedup vs baseline: 2.9841x; 2.9841x over previous
#include <cuda_runtime.h>
#include <math.h>
#include <stdint.h>

#define D_MODEL 512
#define NHEAD   8
#define DK      64
#define BATCH   8
#define SEQ     2048
#define BH      (BATCH * NHEAD)      // 64
#define MROWS   (BATCH * SEQ)        // 16384

// Scratch: head-split projected q/k/v and attention output, [BH][SEQ][DK]
__device__ float g_q[(size_t)BH * SEQ * DK];
__device__ float g_k[(size_t)BH * SEQ * DK];
__device__ float g_v[(size_t)BH * SEQ * DK];
__device__ float g_o[(size_t)BH * SEQ * DK];

// ---------------------------------------------------------------------------
// helpers
// ---------------------------------------------------------------------------
__device__ __forceinline__ float tf32r(float x) {
    float y;
    asm("cvt.rna.tf32.f32 %0, %1;" : "=f"(y) : "f"(x));
    return y;
}
__device__ __forceinline__ uint32_t fu(float x) { return __float_as_uint(x); }

__device__ __forceinline__ void mma8(float d[4],
                                     uint32_t a0, uint32_t a1, uint32_t a2, uint32_t a3,
                                     uint32_t b0, uint32_t b1) {
    asm volatile(
        "mma.sync.aligned.m16n8k8.row.col.f32.tf32.tf32.f32 "
        "{%0,%1,%2,%3},{%4,%5,%6,%7},{%8,%9},{%0,%1,%2,%3};\n"
        : "+f"(d[0]), "+f"(d[1]), "+f"(d[2]), "+f"(d[3])
        : "r"(a0), "r"(a1), "r"(a2), "r"(a3), "r"(b0), "r"(b1));
}

// ---------------------------------------------------------------------------
// Projection GEMM (tf32 tensor cores): dst = X @ W^T + b, head-split scatter.
// Block tile 128x128, 8 warps, warp tile 64x32, k-chunk 16.
// smem ld = 20 -> conflict-free frag loads (banks 20r+c distinct).
// ---------------------------------------------------------------------------
#define GLD 20

__global__ void gemm_qkv_tc(const float* __restrict__ Qx,
                            const float* __restrict__ Kx,
                            const float* __restrict__ Vx,
                            const float* __restrict__ Wq,
                            const float* __restrict__ Wk,
                            const float* __restrict__ Wv,
                            const float* __restrict__ bq,
                            const float* __restrict__ bk,
                            const float* __restrict__ bv)
{
    __shared__ float sA[128 * GLD];
    __shared__ float sB[128 * GLD];

    const int z = blockIdx.z;
    const float* X    = (z == 0) ? Qx : (z == 1) ? Kx : Vx;
    const float* W    = (z == 0) ? Wq : (z == 1) ? Wk : Wv;
    const float* bias = (z == 0) ? bq : (z == 1) ? bk : bv;
    float* dst        = (z == 0) ? g_q : (z == 1) ? g_k : g_v;

    const int bm = blockIdx.x * 128;
    const int bn = blockIdx.y * 128;
    const int t    = threadIdx.x;
    const int lane = t & 31;
    const int wid  = t >> 5;
    const int wm   = wid & 1;        // 0..1 -> M offset 64*wm
    const int wn   = wid >> 1;       // 0..3 -> N offset 32*wn
    const int lr   = lane >> 2;      // 0..7
    const int lc   = lane & 3;       // 0..3

    float acc[4][4][4];
#pragma unroll
    for (int i = 0; i < 4; i++)
#pragma unroll
        for (int j = 0; j < 4; j++)
#pragma unroll
            for (int e = 0; e < 4; e++) acc[i][j][e] = 0.f;

    for (int kc = 0; kc < D_MODEL; kc += 16) {
#pragma unroll
        for (int j = 0; j < 2; j++) {
            int v  = t + 256 * j;
            int m  = v >> 2;
            int kq = v & 3;
            float4 a4 = *(const float4*)&X[(size_t)(bm + m) * D_MODEL + kc + 4 * kq];
            a4.x = tf32r(a4.x); a4.y = tf32r(a4.y); a4.z = tf32r(a4.z); a4.w = tf32r(a4.w);
            *(float4*)&sA[m * GLD + 4 * kq] = a4;
            float4 b4 = *(const float4*)&W[(size_t)(bn + m) * D_MODEL + kc + 4 * kq];
            b4.x = tf32r(b4.x); b4.y = tf32r(b4.y); b4.z = tf32r(b4.z); b4.w = tf32r(b4.w);
            *(float4*)&sB[m * GLD + 4 * kq] = b4;
        }
        __syncthreads();

#pragma unroll
        for (int k8 = 0; k8 < 2; k8++) {
            uint32_t a[4][4], b[4][2];
#pragma unroll
            for (int mf = 0; mf < 4; mf++) {
                const float* p = &sA[(64 * wm + 16 * mf + lr) * GLD + k8 * 8 + lc];
                a[mf][0] = fu(p[0]);
                a[mf][1] = fu(p[8 * GLD]);
                a[mf][2] = fu(p[4]);
                a[mf][3] = fu(p[8 * GLD + 4]);
            }
#pragma unroll
            for (int nf = 0; nf < 4; nf++) {
                const float* p = &sB[(32 * wn + 8 * nf + lr) * GLD + k8 * 8 + lc];
                b[nf][0] = fu(p[0]);
                b[nf][1] = fu(p[4]);
            }
#pragma unroll
            for (int mf = 0; mf < 4; mf++)
#pragma unroll
                for (int nf = 0; nf < 4; nf++)
                    mma8(acc[mf][nf], a[mf][0], a[mf][1], a[mf][2], a[mf][3],
                         b[nf][0], b[nf][1]);
        }
        __syncthreads();
    }

    // epilogue: bias + head-split scatter (float2, dk-contiguous)
#pragma unroll
    for (int mf = 0; mf < 4; mf++) {
        int r0 = bm + 64 * wm + 16 * mf + lr;
#pragma unroll
        for (int nf = 0; nf < 4; nf++) {
            int n  = bn + 32 * wn + 8 * nf + 2 * lc;
            float bi0 = bias[n], bi1 = bias[n + 1];
            int h = n >> 6, d = n & 63;
#pragma unroll
            for (int rr = 0; rr < 2; rr++) {
                int r = r0 + 8 * rr;
                int bb = r >> 11, s = r & (SEQ - 1);
                float2 v2;
                v2.x = acc[mf][nf][2 * rr + 0] + bi0;
                v2.y = acc[mf][nf][2 * rr + 1] + bi1;
                *(float2*)&dst[((size_t)(bb * NHEAD + h) * SEQ + s) * DK + d] = v2;
            }
        }
    }
}

// ---------------------------------------------------------------------------
// Flash attention with tf32 tensor cores.
// Block = (head, 64 q-rows), 4 warps, warp owns 16 q-rows.
// smem: sQ[64][68] | sKP[64][68] (K tile, reused as P) | sV[64][72]
// ld=68 -> conflict-free for Q/K/P frag patterns; ld=72 for V pattern.
// ---------------------------------------------------------------------------
#define ALDQ 68
#define ALDV 72
#define FLASH_SMEM ((64 * ALDQ + 64 * ALDQ + 64 * ALDV) * 4)

__global__ void flash_tc(const int* __restrict__ mask)
{
    extern __shared__ float sm[];
    float* sQ  = sm;                    // 64*68
    float* sKP = sm + 64 * ALDQ;        // 64*68
    float* sV  = sKP + 64 * ALDQ;       // 64*72

    const int bh = blockIdx.y;
    const int qt = blockIdx.x;
    const float* qp = g_q + ((size_t)bh * SEQ + qt * 64) * DK;
    const float* kp = g_k + (size_t)bh * SEQ * DK;
    const float* vp = g_v + (size_t)bh * SEQ * DK;

    const int t    = threadIdx.x;
    const int lane = t & 31;
    const int wid  = t >> 5;       // 4 warps
    const int m0   = wid * 16;
    const int lr   = lane >> 2;
    const int lc   = lane & 3;

    // load Q tile (convert to tf32)
#pragma unroll
    for (int j = 0; j < 8; j++) {
        int v = t + 128 * j;
        int r = v >> 4, c4 = v & 15;
        float4 q4 = *(const float4*)&qp[(size_t)r * DK + 4 * c4];
        q4.x = tf32r(q4.x); q4.y = tf32r(q4.y); q4.z = tf32r(q4.z); q4.w = tf32r(q4.w);
        *(float4*)&sQ[r * ALDQ + 4 * c4] = q4;
    }

    float m_i[2] = {-INFINITY, -INFINITY};
    float l_i[2] = {0.f, 0.f};
    float o[8][4];
#pragma unroll
    for (int f = 0; f < 8; f++)
#pragma unroll
        for (int e = 0; e < 4; e++) o[f][e] = 0.f;

    const int r0g = qt * 64 + m0 + lr;
    const int r1g = r0g + 8;
    __syncthreads();

    for (int kt = 0; kt < SEQ / 64; kt++) {
        const float* kpt = kp + (size_t)kt * 64 * DK;
        const float* vpt = vp + (size_t)kt * 64 * DK;
#pragma unroll
        for (int j = 0; j < 8; j++) {
            int v = t + 128 * j;
            int r = v >> 4, c4 = v & 15;
            float4 k4 = *(const float4*)&kpt[(size_t)r * DK + 4 * c4];
            k4.x = tf32r(k4.x); k4.y = tf32r(k4.y); k4.z = tf32r(k4.z); k4.w = tf32r(k4.w);
            *(float4*)&sKP[r * ALDQ + 4 * c4] = k4;
            float4 v4 = *(const float4*)&vpt[(size_t)r * DK + 4 * c4];
            v4.x = tf32r(v4.x); v4.y = tf32r(v4.y); v4.z = tf32r(v4.z); v4.w = tf32r(v4.w);
            *(float4*)&sV[r * ALDV + 4 * c4] = v4;
        }
        __syncthreads();

        // S = Q K^T  (8 n-frags of 16x8)
        float sf[8][4];
#pragma unroll
        for (int f = 0; f < 8; f++)
#pragma unroll
            for (int e = 0; e < 4; e++) sf[f][e] = 0.f;

#pragma unroll
        for (int k8 = 0; k8 < 8; k8++) {
            const float* ap = &sQ[(m0 + lr) * ALDQ + k8 * 8 + lc];
            uint32_t a0 = fu(ap[0]);
            uint32_t a1 = fu(ap[8 * ALDQ]);
            uint32_t a2 = fu(ap[4]);
            uint32_t a3 = fu(ap[8 * ALDQ + 4]);
#pragma unroll
            for (int f = 0; f < 8; f++) {
                const float* bp = &sKP[(8 * f + lr) * ALDQ + k8 * 8 + lc];
                mma8(sf[f], a0, a1, a2, a3, fu(bp[0]), fu(bp[4]));
            }
        }

        // scale + mask + online softmax (C-frag rows lr and lr+8)
        float mx0 = -INFINITY, mx1 = -INFINITY;
#pragma unroll
        for (int f = 0; f < 8; f++) {
            int col = kt * 64 + 8 * f + 2 * lc;
            int2 mm0 = __ldg((const int2*)(mask + (size_t)r0g * SEQ + col));
            int2 mm1 = __ldg((const int2*)(mask + (size_t)r1g * SEQ + col));
            sf[f][0] = mm0.x ? sf[f][0] * 0.125f : -1e30f;
            sf[f][1] = mm0.y ? sf[f][1] * 0.125f : -1e30f;
            sf[f][2] = mm1.x ? sf[f][2] * 0.125f : -1e30f;
            sf[f][3] = mm1.y ? sf[f][3] * 0.125f : -1e30f;
            mx0 = fmaxf(mx0, fmaxf(sf[f][0], sf[f][1]));
            mx1 = fmaxf(mx1, fmaxf(sf[f][2], sf[f][3]));
        }
        mx0 = fmaxf(mx0, __shfl_xor_sync(0xffffffffu, mx0, 1));
        mx0 = fmaxf(mx0, __shfl_xor_sync(0xffffffffu, mx0, 2));
        mx1 = fmaxf(mx1, __shfl_xor_sync(0xffffffffu, mx1, 1));
        mx1 = fmaxf(mx1, __shfl_xor_sync(0xffffffffu, mx1, 2));

        float mn0 = fmaxf(m_i[0], mx0);
        float mn1 = fmaxf(m_i[1], mx1);
        float al0 = __expf(m_i[0] - mn0);
        float al1 = __expf(m_i[1] - mn1);
        m_i[0] = mn0; m_i[1] = mn1;

        float rs0 = 0.f, rs1 = 0.f;
#pragma unroll
        for (int f = 0; f < 8; f++) {
            sf[f][0] = __expf(sf[f][0] - mn0);
            sf[f][1] = __expf(sf[f][1] - mn0);
            sf[f][2] = __expf(sf[f][2] - mn1);
            sf[f][3] = __expf(sf[f][3] - mn1);
            rs0 += sf[f][0] + sf[f][1];
            rs1 += sf[f][2] + sf[f][3];
        }
        rs0 += __shfl_xor_sync(0xffffffffu, rs0, 1);
        rs0 += __shfl_xor_sync(0xffffffffu, rs0, 2);
        rs1 += __shfl_xor_sync(0xffffffffu, rs1, 1);
        rs1 += __shfl_xor_sync(0xffffffffu, rs1, 2);
        l_i[0] = l_i[0] * al0 + rs0;
        l_i[1] = l_i[1] * al1 + rs1;

        __syncthreads();  // all warps done reading K -> reuse sKP as P

        // write P (tf32) into sKP; each warp writes only its own 16 rows
        {
            int prow = m0 + lr;
            int pc   = 2 * lc;
#pragma unroll
            for (int f = 0; f < 8; f++) {
                float2 p01, p23;
                p01.x = tf32r(sf[f][0]); p01.y = tf32r(sf[f][1]);
                p23.x = tf32r(sf[f][2]); p23.y = tf32r(sf[f][3]);
                *(float2*)&sKP[prow * ALDQ + 8 * f + pc]       = p01;
                *(float2*)&sKP[(prow + 8) * ALDQ + 8 * f + pc] = p23;
            }
        }
        __syncwarp();     // own-warp P rows only -> warp sync suffices

        // O = O*alpha + P V
#pragma unroll
        for (int f = 0; f < 8; f++) {
            o[f][0] *= al0; o[f][1] *= al0;
            o[f][2] *= al1; o[f][3] *= al1;
        }
#pragma unroll
        for (int k8 = 0; k8 < 8; k8++) {
            const float* ap = &sKP[(m0 + lr) * ALDQ + k8 * 8 + lc];
            uint32_t a0 = fu(ap[0]);
            uint32_t a1 = fu(ap[8 * ALDQ]);
            uint32_t a2 = fu(ap[4]);
            uint32_t a3 = fu(ap[8 * ALDQ + 4]);
#pragma unroll
            for (int f = 0; f < 8; f++) {
                const float* bp = &sV[(k8 * 8 + lc) * ALDV + 8 * f + lr];
                mma8(o[f], a0, a1, a2, a3, fu(bp[0]), fu(bp[4 * ALDV]));
            }
        }
        __syncthreads();  // before next tile overwrites sKP / sV
    }

    // epilogue
    float inv0 = 1.f / l_i[0];
    float inv1 = 1.f / l_i[1];
    float* op = g_o + ((size_t)bh * SEQ + qt * 64) * DK;
    {
        int prow = m0 + lr;
        int pc   = 2 * lc;
#pragma unroll
        for (int f = 0; f < 8; f++) {
            float2 v01, v23;
            v01.x = o[f][0] * inv0; v01.y = o[f][1] * inv0;
            v23.x = o[f][2] * inv1; v23.y = o[f][3] * inv1;
            *(float2*)&op[(size_t)prow * DK + 8 * f + pc]       = v01;
            *(float2*)&op[(size_t)(prow + 8) * DK + 8 * f + pc] = v23;
        }
    }
}

// ---------------------------------------------------------------------------
// Output projection (tf32 tensor cores): out = concat(heads) @ Wo^T + bo
// ---------------------------------------------------------------------------
__global__ void gemm_out_tc(const float* __restrict__ Wo,
                            const float* __restrict__ bo,
                            float* __restrict__ out)
{
    __shared__ float sA[128 * GLD];
    __shared__ float sB[128 * GLD];

    const int bm = blockIdx.x * 128;
    const int bn = blockIdx.y * 128;
    const int t    = threadIdx.x;
    const int lane = t & 31;
    const int wid  = t >> 5;
    const int wm   = wid & 1;
    const int wn   = wid >> 1;
    const int lr   = lane >> 2;
    const int lc   = lane & 3;

    float acc[4][4][4];
#pragma unroll
    for (int i = 0; i < 4; i++)
#pragma unroll
        for (int j = 0; j < 4; j++)
#pragma unroll
            for (int e = 0; e < 4; e++) acc[i][j][e] = 0.f;

    for (int kc = 0; kc < D_MODEL; kc += 16) {
#pragma unroll
        for (int j = 0; j < 2; j++) {
            int v  = t + 256 * j;
            int m  = v >> 2;
            int kq = v & 3;
            // gather from head-split g_o
            int r  = bm + m;
            int bb = r >> 11, s = r & (SEQ - 1);
            int ch = kc + 4 * kq;
            int h = ch >> 6, d = ch & 63;
            float4 a4 = *(const float4*)&g_o[((size_t)(bb * NHEAD + h) * SEQ + s) * DK + d];
            a4.x = tf32r(a4.x); a4.y = tf32r(a4.y); a4.z = tf32r(a4.z); a4.w = tf32r(a4.w);
            *(float4*)&sA[m * GLD + 4 * kq] = a4;
            float4 b4 = *(const float4*)&Wo[(size_t)(bn + m) * D_MODEL + kc + 4 * kq];
            b4.x = tf32r(b4.x); b4.y = tf32r(b4.y); b4.z = tf32r(b4.z); b4.w = tf32r(b4.w);
            *(float4*)&sB[m * GLD + 4 * kq] = b4;
        }
        __syncthreads();

#pragma unroll
        for (int k8 = 0; k8 < 2; k8++) {
            uint32_t a[4][4], b[4][2];
#pragma unroll
            for (int mf = 0; mf < 4; mf++) {
                const float* p = &sA[(64 * wm + 16 * mf + lr) * GLD + k8 * 8 + lc];
                a[mf][0] = fu(p[0]);
                a[mf][1] = fu(p[8 * GLD]);
                a[mf][2] = fu(p[4]);
                a[mf][3] = fu(p[8 * GLD + 4]);
            }
#pragma unroll
            for (int nf = 0; nf < 4; nf++) {
                const float* p = &sB[(32 * wn + 8 * nf + lr) * GLD + k8 * 8 + lc];
                b[nf][0] = fu(p[0]);
                b[nf][1] = fu(p[4]);
            }
#pragma unroll
            for (int mf = 0; mf < 4; mf++)
#pragma unroll
                for (int nf = 0; nf < 4; nf++)
                    mma8(acc[mf][nf], a[mf][0], a[mf][1], a[mf][2], a[mf][3],
                         b[nf][0], b[nf][1]);
        }
        __syncthreads();
    }

#pragma unroll
    for (int mf = 0; mf < 4; mf++) {
        int r0 = bm + 64 * wm + 16 * mf + lr;
#pragma unroll
        for (int nf = 0; nf < 4; nf++) {
            int n = bn + 32 * wn + 8 * nf + 2 * lc;
            float bi0 = bo[n], bi1 = bo[n + 1];
#pragma unroll
            for (int rr = 0; rr < 2; rr++) {
                int r = r0 + 8 * rr;
                float2 v2;
                v2.x = acc[mf][nf][2 * rr + 0] + bi0;
                v2.y = acc[mf][nf][2 * rr + 1] + bi1;
                *(float2*)&out[(size_t)r * D_MODEL + n] = v2;
            }
        }
    }
}

// ---------------------------------------------------------------------------
extern "C" void kernel_launch(void* const* d_in, const int* in_sizes, int n_in,
                              void* d_out, int out_size)
{
    const float* Q    = (const float*)d_in[0];
    const float* K    = (const float*)d_in[1];
    const float* V    = (const float*)d_in[2];
    const int*   mask = (const int*)  d_in[3];
    const float* Wq   = (const float*)d_in[4];
    const float* bq   = (const float*)d_in[5];
    const float* Wk   = (const float*)d_in[6];
    const float* bk   = (const float*)d_in[7];
    const float* Wv   = (const float*)d_in[8];
    const float* bv   = (const float*)d_in[9];
    const float* Wo   = (const float*)d_in[10];
    const float* bo   = (const float*)d_in[11];
    float* out = (float*)d_out;

    cudaFuncSetAttribute(flash_tc,
                         cudaFuncAttributeMaxDynamicSharedMemorySize, FLASH_SMEM);

    dim3 pg(MROWS / 128, D_MODEL / 128, 3);     // 128 x 4 x 3
    gemm_qkv_tc<<<pg, 256>>>(Q, K, V, Wq, Wk, Wv, bq, bk, bv);

    dim3 ag(SEQ / 64, BH);                      // 32 x 64
    flash_tc<<<ag, 128, FLASH_SMEM>>>(mask);

    dim3 og(MROWS / 128, D_MODEL / 128);        // 128 x 4
    gemm_out_tc<<<og, 256>>>(Wo, bo, out);
}

// round 3
// speedup vs baseline: 3.0236x; 1.0132x over previous
#include <cuda_runtime.h>
#include <math.h>
#include <stdint.h>

#define D_MODEL 512
#define NHEAD   8
#define DK      64
#define BATCH   8
#define SEQ     2048
#define BH      (BATCH * NHEAD)      // 64
#define MROWS   (BATCH * SEQ)        // 16384

// Scratch: head-split projected q/k/v (pre-rounded tf32; q pre-scaled) + attn out
__device__ float g_q[(size_t)BH * SEQ * DK];
__device__ float g_k[(size_t)BH * SEQ * DK];
__device__ float g_v[(size_t)BH * SEQ * DK];
__device__ float g_o[(size_t)BH * SEQ * DK];

// ---------------------------------------------------------------------------
// helpers
// ---------------------------------------------------------------------------
__device__ __forceinline__ float tf32r(float x) {
    float y;
    asm("cvt.rna.tf32.f32 %0, %1;" : "=f"(y) : "f"(x));
    return y;
}
__device__ __forceinline__ uint32_t fu(float x) { return __float_as_uint(x); }

__device__ __forceinline__ void mma8(float d[4],
                                     uint32_t a0, uint32_t a1, uint32_t a2, uint32_t a3,
                                     uint32_t b0, uint32_t b1) {
    asm volatile(
        "mma.sync.aligned.m16n8k8.row.col.f32.tf32.tf32.f32 "
        "{%0,%1,%2,%3},{%4,%5,%6,%7},{%8,%9},{%0,%1,%2,%3};\n"
        : "+f"(d[0]), "+f"(d[1]), "+f"(d[2]), "+f"(d[3])
        : "r"(a0), "r"(a1), "r"(a2), "r"(a3), "r"(b0), "r"(b1));
}

// ---------------------------------------------------------------------------
// Projection GEMM (tf32 TC): dst = X @ W^T + b, head-split scatter, stored
// tf32-rounded (Q additionally pre-scaled by 1/sqrt(dk) = 0.125).
// ---------------------------------------------------------------------------
#define GLD 20

__global__ void gemm_qkv_tc(const float* __restrict__ Qx,
                            const float* __restrict__ Kx,
                            const float* __restrict__ Vx,
                            const float* __restrict__ Wq,
                            const float* __restrict__ Wk,
                            const float* __restrict__ Wv,
                            const float* __restrict__ bq,
                            const float* __restrict__ bk,
                            const float* __restrict__ bv)
{
    __shared__ float sA[128 * GLD];
    __shared__ float sB[128 * GLD];

    const int z = blockIdx.z;
    const float* X    = (z == 0) ? Qx : (z == 1) ? Kx : Vx;
    const float* W    = (z == 0) ? Wq : (z == 1) ? Wk : Wv;
    const float* bias = (z == 0) ? bq : (z == 1) ? bk : bv;
    float* dst        = (z == 0) ? g_q : (z == 1) ? g_k : g_v;
    const float scl   = (z == 0) ? 0.125f : 1.0f;

    const int bm = blockIdx.x * 128;
    const int bn = blockIdx.y * 128;
    const int t    = threadIdx.x;
    const int lane = t & 31;
    const int wid  = t >> 5;
    const int wm   = wid & 1;
    const int wn   = wid >> 1;
    const int lr   = lane >> 2;
    const int lc   = lane & 3;

    float acc[4][4][4];
#pragma unroll
    for (int i = 0; i < 4; i++)
#pragma unroll
        for (int j = 0; j < 4; j++)
#pragma unroll
            for (int e = 0; e < 4; e++) acc[i][j][e] = 0.f;

    for (int kc = 0; kc < D_MODEL; kc += 16) {
#pragma unroll
        for (int j = 0; j < 2; j++) {
            int v  = t + 256 * j;
            int m  = v >> 2;
            int kq = v & 3;
            float4 a4 = *(const float4*)&X[(size_t)(bm + m) * D_MODEL + kc + 4 * kq];
            a4.x = tf32r(a4.x); a4.y = tf32r(a4.y); a4.z = tf32r(a4.z); a4.w = tf32r(a4.w);
            *(float4*)&sA[m * GLD + 4 * kq] = a4;
            float4 b4 = *(const float4*)&W[(size_t)(bn + m) * D_MODEL + kc + 4 * kq];
            b4.x = tf32r(b4.x); b4.y = tf32r(b4.y); b4.z = tf32r(b4.z); b4.w = tf32r(b4.w);
            *(float4*)&sB[m * GLD + 4 * kq] = b4;
        }
        __syncthreads();

#pragma unroll
        for (int k8 = 0; k8 < 2; k8++) {
            uint32_t a[4][4], b[4][2];
#pragma unroll
            for (int mf = 0; mf < 4; mf++) {
                const float* p = &sA[(64 * wm + 16 * mf + lr) * GLD + k8 * 8 + lc];
                a[mf][0] = fu(p[0]);
                a[mf][1] = fu(p[8 * GLD]);
                a[mf][2] = fu(p[4]);
                a[mf][3] = fu(p[8 * GLD + 4]);
            }
#pragma unroll
            for (int nf = 0; nf < 4; nf++) {
                const float* p = &sB[(32 * wn + 8 * nf + lr) * GLD + k8 * 8 + lc];
                b[nf][0] = fu(p[0]);
                b[nf][1] = fu(p[4]);
            }
#pragma unroll
            for (int mf = 0; mf < 4; mf++)
#pragma unroll
                for (int nf = 0; nf < 4; nf++)
                    mma8(acc[mf][nf], a[mf][0], a[mf][1], a[mf][2], a[mf][3],
                         b[nf][0], b[nf][1]);
        }
        __syncthreads();
    }

#pragma unroll
    for (int mf = 0; mf < 4; mf++) {
        int r0 = bm + 64 * wm + 16 * mf + lr;
#pragma unroll
        for (int nf = 0; nf < 4; nf++) {
            int n  = bn + 32 * wn + 8 * nf + 2 * lc;
            float bi0 = bias[n], bi1 = bias[n + 1];
            int h = n >> 6, d = n & 63;
#pragma unroll
            for (int rr = 0; rr < 2; rr++) {
                int r = r0 + 8 * rr;
                int bb = r >> 11, s = r & (SEQ - 1);
                float2 v2;
                v2.x = tf32r((acc[mf][nf][2 * rr + 0] + bi0) * scl);
                v2.y = tf32r((acc[mf][nf][2 * rr + 1] + bi1) * scl);
                *(float2*)&dst[((size_t)(bb * NHEAD + h) * SEQ + s) * DK + d] = v2;
            }
        }
    }
}

// ---------------------------------------------------------------------------
// Flash attention v2: BM=128, BN=64, 8 warps. Q frags in registers.
// Fragment-permuted smem layouts:
//   Kp/Vp: [f][k8][lane] float2, k8-group stride 33 float2 -> B-frag = 1 LDS.64
//   Pp:    [warp][k8][lane] float4, stride 33 float4        -> A-frag = 1 LDS.128
// Pp region doubles as Q staging at prologue.
// ---------------------------------------------------------------------------
#define PP_F4   2112                 // 8*264 = 2112 float4 slots
#define KP_F2   2112                 // 64*33 = 2112 float2 slots
#define FLASH_SMEM ((PP_F4 * 4 + KP_F2 * 2 + KP_F2 * 2) * 4)   // 67584 B

__global__ void __launch_bounds__(256, 2) flash_tc2(const int* __restrict__ mask)
{
    extern __shared__ float sm[];
    float* sP  = sm;                       // Pp (and Q staging): 8448 floats
    float* sKp = sm + PP_F4 * 4;           // 4224 floats
    float* sVp = sKp + KP_F2 * 2;          // 4224 floats

    const int bh = blockIdx.y;
    const int qt = blockIdx.x;
    const float* qp = g_q + ((size_t)bh * SEQ + qt * 128) * DK;
    const float* kp = g_k + (size_t)bh * SEQ * DK;
    const float* vp = g_v + (size_t)bh * SEQ * DK;

    const int t    = threadIdx.x;
    const int lane = t & 31;
    const int wid  = t >> 5;               // 8 warps
    const int m0   = wid * 16;
    const int lr   = lane >> 2;
    const int lc   = lane & 3;

    // ---- stage Q tile (pre-rounded, pre-scaled) and pull A-frags to regs ----
#pragma unroll
    for (int j = 0; j < 8; j++) {
        int v = t + 256 * j;               // 2048 float4 = 128x64
        int r = v >> 4, c4 = v & 15;
        *(float4*)&sP[r * 64 + 4 * c4] = *(const float4*)&qp[(size_t)r * DK + 4 * c4];
    }
    __syncthreads();

    float qa[8][4];
#pragma unroll
    for (int k8 = 0; k8 < 8; k8++) {
        const float* p = &sP[(m0 + lr) * 64 + 8 * k8 + lc];
        qa[k8][0] = p[0];
        qa[k8][1] = p[8 * 64];
        qa[k8][2] = p[4];
        qa[k8][3] = p[8 * 64 + 4];
    }

    float m_i[2] = {-INFINITY, -INFINITY};
    float l_i[2] = {0.f, 0.f};
    float o[8][4];
#pragma unroll
    for (int f = 0; f < 8; f++)
#pragma unroll
        for (int e = 0; e < 4; e++) o[f][e] = 0.f;

    const int r0g = qt * 128 + m0 + lr;
    const int r1g = r0g + 8;

    // loader index precompute
    const int krb = t >> 4;                // K: row base, cols 4*(t&15)
    const int kcb = 4 * (t & 15);
    const int vn  = t & 63;                // V: row, col quarter 16*(t>>6)
    const int vdb = 16 * (t >> 6);

    for (int kt = 0; kt < SEQ / 64; kt++) {
        const float* kpt = kp + (size_t)kt * 64 * DK;
        const float* vpt = vp + (size_t)kt * 64 * DK;

        // ---- K tile -> Kp (permuted) ----
#pragma unroll
        for (int p = 0; p < 4; p++) {
            int r = krb + 16 * p;
            float4 kv = *(const float4*)&kpt[(size_t)r * DK + kcb];
#pragma unroll
            for (int i = 0; i < 4; i++) {
                int c = kcb + i;
                int idx2 = ((r >> 3) * 8 + (c >> 3)) * 33 + 4 * (r & 7) + (c & 3);
                sKp[2 * idx2 + ((c >> 2) & 1)] = ((const float*)&kv)[i];
            }
        }
        // ---- V tile -> Vp (permuted) ----
#pragma unroll
        for (int j = 0; j < 4; j++) {
            float4 vv = *(const float4*)&vpt[(size_t)vn * DK + vdb + 4 * j];
#pragma unroll
            for (int i = 0; i < 4; i++) {
                int d = vdb + 4 * j + i;
                int idx2 = ((d >> 3) * 8 + (vn >> 3)) * 33 + 4 * (d & 7) + (vn & 3);
                sVp[2 * idx2 + ((vn >> 2) & 1)] = ((const float*)&vv)[i];
            }
        }
        __syncthreads();

        // ---- S = Q K^T ----
        float sf[8][4];
#pragma unroll
        for (int f = 0; f < 8; f++)
#pragma unroll
            for (int e = 0; e < 4; e++) sf[f][e] = 0.f;

#pragma unroll
        for (int k8 = 0; k8 < 8; k8++) {
            uint32_t a0 = fu(qa[k8][0]), a1 = fu(qa[k8][1]);
            uint32_t a2 = fu(qa[k8][2]), a3 = fu(qa[k8][3]);
#pragma unroll
            for (int f = 0; f < 8; f++) {
                float2 b = *(const float2*)&sKp[2 * ((f * 8 + k8) * 33 + lane)];
                mma8(sf[f], a0, a1, a2, a3, fu(b.x), fu(b.y));
            }
        }

        // ---- mask + online softmax (Q already scaled by 0.125) ----
        float mx0 = -INFINITY, mx1 = -INFINITY;
#pragma unroll
        for (int f = 0; f < 8; f++) {
            int col = kt * 64 + 8 * f + 2 * lc;
            int2 mm0 = __ldg((const int2*)(mask + (size_t)r0g * SEQ + col));
            int2 mm1 = __ldg((const int2*)(mask + (size_t)r1g * SEQ + col));
            sf[f][0] = mm0.x ? sf[f][0] : -1e30f;
            sf[f][1] = mm0.y ? sf[f][1] : -1e30f;
            sf[f][2] = mm1.x ? sf[f][2] : -1e30f;
            sf[f][3] = mm1.y ? sf[f][3] : -1e30f;
            mx0 = fmaxf(mx0, fmaxf(sf[f][0], sf[f][1]));
            mx1 = fmaxf(mx1, fmaxf(sf[f][2], sf[f][3]));
        }
        mx0 = fmaxf(mx0, __shfl_xor_sync(0xffffffffu, mx0, 1));
        mx0 = fmaxf(mx0, __shfl_xor_sync(0xffffffffu, mx0, 2));
        mx1 = fmaxf(mx1, __shfl_xor_sync(0xffffffffu, mx1, 1));
        mx1 = fmaxf(mx1, __shfl_xor_sync(0xffffffffu, mx1, 2));

        float mn0 = fmaxf(m_i[0], mx0);
        float mn1 = fmaxf(m_i[1], mx1);
        float al0 = __expf(m_i[0] - mn0);
        float al1 = __expf(m_i[1] - mn1);
        m_i[0] = mn0; m_i[1] = mn1;

        float rs0 = 0.f, rs1 = 0.f;
#pragma unroll
        for (int f = 0; f < 8; f++) {
            sf[f][0] = __expf(sf[f][0] - mn0);
            sf[f][1] = __expf(sf[f][1] - mn0);
            sf[f][2] = __expf(sf[f][2] - mn1);
            sf[f][3] = __expf(sf[f][3] - mn1);
            rs0 += sf[f][0] + sf[f][1];
            rs1 += sf[f][2] + sf[f][3];
        }
        rs0 += __shfl_xor_sync(0xffffffffu, rs0, 1);
        rs0 += __shfl_xor_sync(0xffffffffu, rs0, 2);
        rs1 += __shfl_xor_sync(0xffffffffu, rs1, 1);
        rs1 += __shfl_xor_sync(0xffffffffu, rs1, 2);
        l_i[0] = l_i[0] * al0 + rs0;
        l_i[1] = l_i[1] * al1 + rs1;

        // ---- P -> Pp (A-frag permuted, own-warp slice only) ----
#pragma unroll
        for (int f = 0; f < 8; f++) {
#pragma unroll
            for (int e = 0; e < 4; e++) {
                int cw   = 2 * lc + (e & 1);
                int slot = (e >> 1) + ((cw >= 4) ? 2 : 0);
                int lnp  = 4 * lr + (cw & 3);
                sP[(wid * 264 + f * 33 + lnp) * 4 + slot] = tf32r(sf[f][e]);
            }
        }
        __syncwarp();

        // ---- O = O*alpha + P V ----
#pragma unroll
        for (int f = 0; f < 8; f++) {
            o[f][0] *= al0; o[f][1] *= al0;
            o[f][2] *= al1; o[f][3] *= al1;
        }
#pragma unroll
        for (int k8 = 0; k8 < 8; k8++) {
            float4 pa = *(const float4*)&sP[(wid * 264 + k8 * 33 + lane) * 4];
            uint32_t a0 = fu(pa.x), a1 = fu(pa.y), a2 = fu(pa.z), a3 = fu(pa.w);
#pragma unroll
            for (int f = 0; f < 8; f++) {
                float2 b = *(const float2*)&sVp[2 * ((f * 8 + k8) * 33 + lane)];
                mma8(o[f], a0, a1, a2, a3, fu(b.x), fu(b.y));
            }
        }
        __syncthreads();   // Kp/Vp fully consumed before next tile load
    }

    // ---- epilogue (pre-round for out_proj) ----
    float inv0 = 1.f / l_i[0];
    float inv1 = 1.f / l_i[1];
    float* op = g_o + ((size_t)bh * SEQ + qt * 128) * DK;
    {
        int prow = m0 + lr;
        int pc   = 2 * lc;
#pragma unroll
        for (int f = 0; f < 8; f++) {
            float2 v01, v23;
            v01.x = tf32r(o[f][0] * inv0); v01.y = tf32r(o[f][1] * inv0);
            v23.x = tf32r(o[f][2] * inv1); v23.y = tf32r(o[f][3] * inv1);
            *(float2*)&op[(size_t)prow * DK + 8 * f + pc]       = v01;
            *(float2*)&op[(size_t)(prow + 8) * DK + 8 * f + pc] = v23;
        }
    }
}

// ---------------------------------------------------------------------------
// Output projection (tf32 TC): out = concat(heads) @ Wo^T + bo
// g_o is pre-rounded -> no cvt on the A path.
// ---------------------------------------------------------------------------
__global__ void gemm_out_tc(const float* __restrict__ Wo,
                            const float* __restrict__ bo,
                            float* __restrict__ out)
{
    __shared__ float sA[128 * GLD];
    __shared__ float sB[128 * GLD];

    const int bm = blockIdx.x * 128;
    const int bn = blockIdx.y * 128;
    const int t    = threadIdx.x;
    const int lane = t & 31;
    const int wid  = t >> 5;
    const int wm   = wid & 1;
    const int wn   = wid >> 1;
    const int lr   = lane >> 2;
    const int lc   = lane & 3;

    float acc[4][4][4];
#pragma unroll
    for (int i = 0; i < 4; i++)
#pragma unroll
        for (int j = 0; j < 4; j++)
#pragma unroll
            for (int e = 0; e < 4; e++) acc[i][j][e] = 0.f;

    for (int kc = 0; kc < D_MODEL; kc += 16) {
#pragma unroll
        for (int j = 0; j < 2; j++) {
            int v  = t + 256 * j;
            int m  = v >> 2;
            int kq = v & 3;
            int r  = bm + m;
            int bb = r >> 11, s = r & (SEQ - 1);
            int ch = kc + 4 * kq;
            int h = ch >> 6, d = ch & 63;
            *(float4*)&sA[m * GLD + 4 * kq] =
                *(const float4*)&g_o[((size_t)(bb * NHEAD + h) * SEQ + s) * DK + d];
            float4 b4 = *(const float4*)&Wo[(size_t)(bn + m) * D_MODEL + kc + 4 * kq];
            b4.x = tf32r(b4.x); b4.y = tf32r(b4.y); b4.z = tf32r(b4.z); b4.w = tf32r(b4.w);
            *(float4*)&sB[m * GLD + 4 * kq] = b4;
        }
        __syncthreads();

#pragma unroll
        for (int k8 = 0; k8 < 2; k8++) {
            uint32_t a[4][4], b[4][2];
#pragma unroll
            for (int mf = 0; mf < 4; mf++) {
                const float* p = &sA[(64 * wm + 16 * mf + lr) * GLD + k8 * 8 + lc];
                a[mf][0] = fu(p[0]);
                a[mf][1] = fu(p[8 * GLD]);
                a[mf][2] = fu(p[4]);
                a[mf][3] = fu(p[8 * GLD + 4]);
            }
#pragma unroll
            for (int nf = 0; nf < 4; nf++) {
                const float* p = &sB[(32 * wn + 8 * nf + lr) * GLD + k8 * 8 + lc];
                b[nf][0] = fu(p[0]);
                b[nf][1] = fu(p[4]);
            }
#pragma unroll
            for (int mf = 0; mf < 4; mf++)
#pragma unroll
                for (int nf = 0; nf < 4; nf++)
                    mma8(acc[mf][nf], a[mf][0], a[mf][1], a[mf][2], a[mf][3],
                         b[nf][0], b[nf][1]);
        }
        __syncthreads();
    }

#pragma unroll
    for (int mf = 0; mf < 4; mf++) {
        int r0 = bm + 64 * wm + 16 * mf + lr;
#pragma unroll
        for (int nf = 0; nf < 4; nf++) {
            int n = bn + 32 * wn + 8 * nf + 2 * lc;
            float bi0 = bo[n], bi1 = bo[n + 1];
#pragma unroll
            for (int rr = 0; rr < 2; rr++) {
                int r = r0 + 8 * rr;
                float2 v2;
                v2.x = acc[mf][nf][2 * rr + 0] + bi0;
                v2.y = acc[mf][nf][2 * rr + 1] + bi1;
                *(float2*)&out[(size_t)r * D_MODEL + n] = v2;
            }
        }
    }
}

// ---------------------------------------------------------------------------
extern "C" void kernel_launch(void* const* d_in, const int* in_sizes, int n_in,
                              void* d_out, int out_size)
{
    const float* Q    = (const float*)d_in[0];
    const float* K    = (const float*)d_in[1];
    const float* V    = (const float*)d_in[2];
    const int*   mask = (const int*)  d_in[3];
    const float* Wq   = (const float*)d_in[4];
    const float* bq   = (const float*)d_in[5];
    const float* Wk   = (const float*)d_in[6];
    const float* bk   = (const float*)d_in[7];
    const float* Wv   = (const float*)d_in[8];
    const float* bv   = (const float*)d_in[9];
    const float* Wo   = (const float*)d_in[10];
    const float* bo   = (const float*)d_in[11];
    float* out = (float*)d_out;

    cudaFuncSetAttribute(flash_tc2,
                         cudaFuncAttributeMaxDynamicSharedMemorySize, FLASH_SMEM);

    dim3 pg(MROWS / 128, D_MODEL / 128, 3);     // 128 x 4 x 3
    gemm_qkv_tc<<<pg, 256>>>(Q, K, V, Wq, Wk, Wv, bq, bk, bv);

    dim3 ag(SEQ / 128, BH);                     // 16 x 64
    flash_tc2<<<ag, 256, FLASH_SMEM>>>(mask);

    dim3 og(MROWS / 128, D_MODEL / 128);        // 128 x 4
    gemm_out_tc<<<og, 256>>>(Wo, bo, out);
}

// round 4
// speedup vs baseline: 4.0292x; 1.3326x over previous
#include <cuda_runtime.h>
#include <math.h>
#include <stdint.h>

#define D_MODEL 512
#define NHEAD   8
#define DK      64
#define BATCH   8
#define SEQ     2048
#define BH      (BATCH * NHEAD)      // 64
#define MROWS   (BATCH * SEQ)        // 16384

// Scratch: head-split projected q/k/v (tf32-rounded; q pre-scaled by 0.125*log2e)
__device__ float g_q[(size_t)BH * SEQ * DK];
__device__ float g_k[(size_t)BH * SEQ * DK];
__device__ float g_v[(size_t)BH * SEQ * DK];
__device__ float g_o[(size_t)BH * SEQ * DK];
__device__ unsigned g_mb[(size_t)SEQ * (SEQ / 32)];   // packed mask bits

// ---------------------------------------------------------------------------
// helpers
// ---------------------------------------------------------------------------
__device__ __forceinline__ float tf32r(float x) {
    float y;
    asm("cvt.rna.tf32.f32 %0, %1;" : "=f"(y) : "f"(x));
    return y;
}
__device__ __forceinline__ uint32_t fu(float x) { return __float_as_uint(x); }

__device__ __forceinline__ void mma8(float d[4],
                                     uint32_t a0, uint32_t a1, uint32_t a2, uint32_t a3,
                                     uint32_t b0, uint32_t b1) {
    asm volatile(
        "mma.sync.aligned.m16n8k8.row.col.f32.tf32.tf32.f32 "
        "{%0,%1,%2,%3},{%4,%5,%6,%7},{%8,%9},{%0,%1,%2,%3};\n"
        : "+f"(d[0]), "+f"(d[1]), "+f"(d[2]), "+f"(d[3])
        : "r"(a0), "r"(a1), "r"(a2), "r"(a3), "r"(b0), "r"(b1));
}

__device__ __forceinline__ void cpa16(float* dst, const float* src) {
    unsigned d = (unsigned)__cvta_generic_to_shared(dst);
    asm volatile("cp.async.cg.shared.global [%0], [%1], 16;\n" :: "r"(d), "l"(src));
}
__device__ __forceinline__ void cpa_commit() {
    asm volatile("cp.async.commit_group;\n" ::: "memory");
}
template <int N> __device__ __forceinline__ void cpa_wait() {
    asm volatile("cp.async.wait_group %0;\n" :: "n"(N) : "memory");
}

// ---------------------------------------------------------------------------
// Pack mask ints -> bits. warp w handles row r = w>>6, word w&63.
// ---------------------------------------------------------------------------
__global__ void pack_mask(const int* __restrict__ mask)
{
    int warp = (blockIdx.x * blockDim.x + threadIdx.x) >> 5;
    int lane = threadIdx.x & 31;
    int r = warp >> 6, w = warp & 63;
    int m = mask[(size_t)r * SEQ + w * 32 + lane];
    unsigned bits = __ballot_sync(0xffffffffu, m != 0);
    if (lane == 0) g_mb[warp] = bits;
}

// ---------------------------------------------------------------------------
// Projection GEMM (tf32 TC): dst = X @ W^T + b, head-split scatter, stored
// tf32-rounded (Q pre-scaled by 0.125*log2e for exp2-domain softmax).
// ---------------------------------------------------------------------------
#define GLD 20
#define QSCL (0.125f * 1.4426950408889634f)

__global__ void gemm_qkv_tc(const float* __restrict__ Qx,
                            const float* __restrict__ Kx,
                            const float* __restrict__ Vx,
                            const float* __restrict__ Wq,
                            const float* __restrict__ Wk,
                            const float* __restrict__ Wv,
                            const float* __restrict__ bq,
                            const float* __restrict__ bk,
                            const float* __restrict__ bv)
{
    __shared__ float sA[128 * GLD];
    __shared__ float sB[128 * GLD];

    const int z = blockIdx.z;
    const float* X    = (z == 0) ? Qx : (z == 1) ? Kx : Vx;
    const float* W    = (z == 0) ? Wq : (z == 1) ? Wk : Wv;
    const float* bias = (z == 0) ? bq : (z == 1) ? bk : bv;
    float* dst        = (z == 0) ? g_q : (z == 1) ? g_k : g_v;
    const float scl   = (z == 0) ? QSCL : 1.0f;

    const int bm = blockIdx.x * 128;
    const int bn = blockIdx.y * 128;
    const int t    = threadIdx.x;
    const int lane = t & 31;
    const int wid  = t >> 5;
    const int wm   = wid & 1;
    const int wn   = wid >> 1;
    const int lr   = lane >> 2;
    const int lc   = lane & 3;

    float acc[4][4][4];
#pragma unroll
    for (int i = 0; i < 4; i++)
#pragma unroll
        for (int j = 0; j < 4; j++)
#pragma unroll
            for (int e = 0; e < 4; e++) acc[i][j][e] = 0.f;

    for (int kc = 0; kc < D_MODEL; kc += 16) {
#pragma unroll
        for (int j = 0; j < 2; j++) {
            int v  = t + 256 * j;
            int m  = v >> 2;
            int kq = v & 3;
            float4 a4 = *(const float4*)&X[(size_t)(bm + m) * D_MODEL + kc + 4 * kq];
            a4.x = tf32r(a4.x); a4.y = tf32r(a4.y); a4.z = tf32r(a4.z); a4.w = tf32r(a4.w);
            *(float4*)&sA[m * GLD + 4 * kq] = a4;
            float4 b4 = *(const float4*)&W[(size_t)(bn + m) * D_MODEL + kc + 4 * kq];
            b4.x = tf32r(b4.x); b4.y = tf32r(b4.y); b4.z = tf32r(b4.z); b4.w = tf32r(b4.w);
            *(float4*)&sB[m * GLD + 4 * kq] = b4;
        }
        __syncthreads();

#pragma unroll
        for (int k8 = 0; k8 < 2; k8++) {
            uint32_t a[4][4], b[4][2];
#pragma unroll
            for (int mf = 0; mf < 4; mf++) {
                const float* p = &sA[(64 * wm + 16 * mf + lr) * GLD + k8 * 8 + lc];
                a[mf][0] = fu(p[0]);
                a[mf][1] = fu(p[8 * GLD]);
                a[mf][2] = fu(p[4]);
                a[mf][3] = fu(p[8 * GLD + 4]);
            }
#pragma unroll
            for (int nf = 0; nf < 4; nf++) {
                const float* p = &sB[(32 * wn + 8 * nf + lr) * GLD + k8 * 8 + lc];
                b[nf][0] = fu(p[0]);
                b[nf][1] = fu(p[4]);
            }
#pragma unroll
            for (int mf = 0; mf < 4; mf++)
#pragma unroll
                for (int nf = 0; nf < 4; nf++)
                    mma8(acc[mf][nf], a[mf][0], a[mf][1], a[mf][2], a[mf][3],
                         b[nf][0], b[nf][1]);
        }
        __syncthreads();
    }

#pragma unroll
    for (int mf = 0; mf < 4; mf++) {
        int r0 = bm + 64 * wm + 16 * mf + lr;
#pragma unroll
        for (int nf = 0; nf < 4; nf++) {
            int n  = bn + 32 * wn + 8 * nf + 2 * lc;
            float bi0 = bias[n], bi1 = bias[n + 1];
            int h = n >> 6, d = n & 63;
#pragma unroll
            for (int rr = 0; rr < 2; rr++) {
                int r = r0 + 8 * rr;
                int bb = r >> 11, s = r & (SEQ - 1);
                float2 v2;
                v2.x = tf32r((acc[mf][nf][2 * rr + 0] + bi0) * scl);
                v2.y = tf32r((acc[mf][nf][2 * rr + 1] + bi1) * scl);
                *(float2*)&dst[((size_t)(bb * NHEAD + h) * SEQ + s) * DK + d] = v2;
            }
        }
    }
}

// ---------------------------------------------------------------------------
// Flash attention v3: BM=128, BN=64, 8 warps, Q frags in regs,
// cp.async double-buffered K/V, bitmask mask, exp2-domain softmax.
// smem: sP (per-warp 16x68, Q staging + P) | sK[2] 64x68 | sV[2] 64x72
// ---------------------------------------------------------------------------
#define KLD 68
#define VLD 72
#define PLD 68
#define SP_FLOATS (8 * 16 * PLD)                 // 8704
#define SK_FLOATS (2 * 64 * KLD)                 // 8704
#define SV_FLOATS (2 * 64 * VLD)                 // 9216
#define FLASH_SMEM ((SP_FLOATS + SK_FLOATS + SV_FLOATS) * 4)   // 106496 B
#define NT (SEQ / 64)

__global__ void __launch_bounds__(256, 2) flash_tc3()
{
    extern __shared__ float sm[];
    float* sP = sm;                          // 8704 floats
    float* sK = sm + SP_FLOATS;              // 2 x 64x68
    float* sV = sK + SK_FLOATS;              // 2 x 64x72

    const int bh = blockIdx.y;
    const int qt = blockIdx.x;
    const float* qp = g_q + ((size_t)bh * SEQ + qt * 128) * DK;
    const float* kp = g_k + (size_t)bh * SEQ * DK;
    const float* vp = g_v + (size_t)bh * SEQ * DK;

    const int t    = threadIdx.x;
    const int lane = t & 31;
    const int wid  = t >> 5;                 // 8 warps
    const int m0   = wid * 16;
    const int lr   = lane >> 2;
    const int lc   = lane & 3;

    float* sPw = sP + wid * 16 * PLD;

    // ---- stage this warp's 16x64 Q rows into its P region, extract frags ----
#pragma unroll
    for (int j = 0; j < 8; j++) {
        int idx = lane + 32 * j;             // 256 float4 per warp
        int r = idx >> 4, c4 = idx & 15;
        *(float4*)&sPw[r * PLD + 4 * c4] =
            *(const float4*)&qp[(size_t)(m0 + r) * DK + 4 * c4];
    }
    __syncwarp();

    float qa[8][4];
#pragma unroll
    for (int k8 = 0; k8 < 8; k8++) {
        const float* p = &sPw[lr * PLD + 8 * k8 + lc];
        qa[k8][0] = p[0];
        qa[k8][1] = p[8 * PLD];
        qa[k8][2] = p[4];
        qa[k8][3] = p[8 * PLD + 4];
    }
    __syncwarp();

    float m_i[2] = {-INFINITY, -INFINITY};
    float l_i[2] = {0.f, 0.f};
    float o[8][4];
#pragma unroll
    for (int f = 0; f < 8; f++)
#pragma unroll
        for (int e = 0; e < 4; e++) o[f][e] = 0.f;

    const int r0g = qt * 128 + m0 + lr;
    const int r1g = r0g + 8;

    // ---- cp.async tile loader ----
    const int ldr = t >> 4;                  // rows r, r+16, r+32, r+48
    const int ldc = 4 * (t & 15);

    auto load_tile = [&](int kt, int buf) {
        const float* kpt = kp + (size_t)kt * 64 * DK;
        const float* vpt = vp + (size_t)kt * 64 * DK;
        float* kb = sK + buf * 64 * KLD;
        float* vb = sV + buf * 64 * VLD;
#pragma unroll
        for (int p = 0; p < 4; p++) {
            int r = ldr + 16 * p;
            cpa16(&kb[r * KLD + ldc], &kpt[(size_t)r * DK + ldc]);
            cpa16(&vb[r * VLD + ldc], &vpt[(size_t)r * DK + ldc]);
        }
    };

    // prologue: tile 0 in flight
    load_tile(0, 0);
    cpa_commit();

    for (int kt = 0; kt < NT; kt++) {
        const int cur = kt & 1;

        // prefetch next tile (or empty group to keep wait counts aligned)
        if (kt + 1 < NT) load_tile(kt + 1, cur ^ 1);
        cpa_commit();
        cpa_wait<1>();          // tile kt resident
        __syncthreads();

        // mask bits for this thread's 2 rows x 64 cols
        uint2 mw0 = *(const uint2*)&g_mb[(size_t)r0g * (SEQ / 32) + kt * 2];
        uint2 mw1 = *(const uint2*)&g_mb[(size_t)r1g * (SEQ / 32) + kt * 2];

        const float* kb = sK + cur * 64 * KLD;
        const float* vb = sV + cur * 64 * VLD;

        // ---- S = Q K^T (log2-domain: Q pre-scaled by 0.125*log2e) ----
        float sf[8][4];
#pragma unroll
        for (int f = 0; f < 8; f++)
#pragma unroll
            for (int e = 0; e < 4; e++) sf[f][e] = 0.f;

#pragma unroll
        for (int k8 = 0; k8 < 8; k8++) {
            uint32_t a0 = fu(qa[k8][0]), a1 = fu(qa[k8][1]);
            uint32_t a2 = fu(qa[k8][2]), a3 = fu(qa[k8][3]);
#pragma unroll
            for (int f = 0; f < 8; f++) {
                const float* bp = &kb[(8 * f + lr) * KLD + 8 * k8 + lc];
                mma8(sf[f], a0, a1, a2, a3, fu(bp[0]), fu(bp[4]));
            }
        }

        // ---- mask (bit test) + running max ----
        float mx0 = -INFINITY, mx1 = -INFINITY;
#pragma unroll
        for (int f = 0; f < 8; f++) {
            unsigned w0 = (f < 4) ? mw0.x : mw0.y;
            unsigned w1 = (f < 4) ? mw1.x : mw1.y;
            int bit = (8 * f + 2 * lc) & 31;
            unsigned t0 = (w0 >> bit) & 3u;
            unsigned t1 = (w1 >> bit) & 3u;
            sf[f][0] = (t0 & 1u) ? sf[f][0] : -1e30f;
            sf[f][1] = (t0 & 2u) ? sf[f][1] : -1e30f;
            sf[f][2] = (t1 & 1u) ? sf[f][2] : -1e30f;
            sf[f][3] = (t1 & 2u) ? sf[f][3] : -1e30f;
            mx0 = fmaxf(mx0, fmaxf(sf[f][0], sf[f][1]));
            mx1 = fmaxf(mx1, fmaxf(sf[f][2], sf[f][3]));
        }
        mx0 = fmaxf(mx0, __shfl_xor_sync(0xffffffffu, mx0, 1));
        mx0 = fmaxf(mx0, __shfl_xor_sync(0xffffffffu, mx0, 2));
        mx1 = fmaxf(mx1, __shfl_xor_sync(0xffffffffu, mx1, 1));
        mx1 = fmaxf(mx1, __shfl_xor_sync(0xffffffffu, mx1, 2));

        float mn0 = fmaxf(m_i[0], mx0);
        float mn1 = fmaxf(m_i[1], mx1);
        float al0 = exp2f(m_i[0] - mn0);
        float al1 = exp2f(m_i[1] - mn1);
        m_i[0] = mn0; m_i[1] = mn1;

        float rs0 = 0.f, rs1 = 0.f;
#pragma unroll
        for (int f = 0; f < 8; f++) {
            sf[f][0] = exp2f(sf[f][0] - mn0);
            sf[f][1] = exp2f(sf[f][1] - mn0);
            sf[f][2] = exp2f(sf[f][2] - mn1);
            sf[f][3] = exp2f(sf[f][3] - mn1);
            rs0 += sf[f][0] + sf[f][1];
            rs1 += sf[f][2] + sf[f][3];
        }
        rs0 += __shfl_xor_sync(0xffffffffu, rs0, 1);
        rs0 += __shfl_xor_sync(0xffffffffu, rs0, 2);
        rs1 += __shfl_xor_sync(0xffffffffu, rs1, 1);
        rs1 += __shfl_xor_sync(0xffffffffu, rs1, 2);
        l_i[0] = l_i[0] * al0 + rs0;
        l_i[1] = l_i[1] * al1 + rs1;

        // ---- P -> own-warp P region (tf32) ----
#pragma unroll
        for (int f = 0; f < 8; f++) {
            float2 p01, p23;
            p01.x = tf32r(sf[f][0]); p01.y = tf32r(sf[f][1]);
            p23.x = tf32r(sf[f][2]); p23.y = tf32r(sf[f][3]);
            *(float2*)&sPw[lr * PLD + 8 * f + 2 * lc]       = p01;
            *(float2*)&sPw[(lr + 8) * PLD + 8 * f + 2 * lc] = p23;
        }
        __syncwarp();

        // ---- O = O*alpha + P V ----
#pragma unroll
        for (int f = 0; f < 8; f++) {
            o[f][0] *= al0; o[f][1] *= al0;
            o[f][2] *= al1; o[f][3] *= al1;
        }
#pragma unroll
        for (int k8 = 0; k8 < 8; k8++) {
            const float* ap = &sPw[lr * PLD + 8 * k8 + lc];
            uint32_t a0 = fu(ap[0]);
            uint32_t a1 = fu(ap[8 * PLD]);
            uint32_t a2 = fu(ap[4]);
            uint32_t a3 = fu(ap[8 * PLD + 4]);
#pragma unroll
            for (int f = 0; f < 8; f++) {
                const float* bp = &vb[(8 * k8 + lc) * VLD + 8 * f + lr];
                mma8(o[f], a0, a1, a2, a3, fu(bp[0]), fu(bp[4 * VLD]));
            }
        }
        __syncthreads();   // everyone done with buf cur before it is refilled
    }

    // ---- epilogue (pre-round for out_proj) ----
    float inv0 = 1.f / l_i[0];
    float inv1 = 1.f / l_i[1];
    float* op = g_o + ((size_t)bh * SEQ + qt * 128) * DK;
    {
        int prow = m0 + lr;
        int pc   = 2 * lc;
#pragma unroll
        for (int f = 0; f < 8; f++) {
            float2 v01, v23;
            v01.x = tf32r(o[f][0] * inv0); v01.y = tf32r(o[f][1] * inv0);
            v23.x = tf32r(o[f][2] * inv1); v23.y = tf32r(o[f][3] * inv1);
            *(float2*)&op[(size_t)prow * DK + 8 * f + pc]       = v01;
            *(float2*)&op[(size_t)(prow + 8) * DK + 8 * f + pc] = v23;
        }
    }
}

// ---------------------------------------------------------------------------
// Output projection (tf32 TC): out = concat(heads) @ Wo^T + bo
// ---------------------------------------------------------------------------
__global__ void gemm_out_tc(const float* __restrict__ Wo,
                            const float* __restrict__ bo,
                            float* __restrict__ out)
{
    __shared__ float sA[128 * GLD];
    __shared__ float sB[128 * GLD];

    const int bm = blockIdx.x * 128;
    const int bn = blockIdx.y * 128;
    const int t    = threadIdx.x;
    const int lane = t & 31;
    const int wid  = t >> 5;
    const int wm   = wid & 1;
    const int wn   = wid >> 1;
    const int lr   = lane >> 2;
    const int lc   = lane & 3;

    float acc[4][4][4];
#pragma unroll
    for (int i = 0; i < 4; i++)
#pragma unroll
        for (int j = 0; j < 4; j++)
#pragma unroll
            for (int e = 0; e < 4; e++) acc[i][j][e] = 0.f;

    for (int kc = 0; kc < D_MODEL; kc += 16) {
#pragma unroll
        for (int j = 0; j < 2; j++) {
            int v  = t + 256 * j;
            int m  = v >> 2;
            int kq = v & 3;
            int r  = bm + m;
            int bb = r >> 11, s = r & (SEQ - 1);
            int ch = kc + 4 * kq;
            int h = ch >> 6, d = ch & 63;
            *(float4*)&sA[m * GLD + 4 * kq] =
                *(const float4*)&g_o[((size_t)(bb * NHEAD + h) * SEQ + s) * DK + d];
            float4 b4 = *(const float4*)&Wo[(size_t)(bn + m) * D_MODEL + kc + 4 * kq];
            b4.x = tf32r(b4.x); b4.y = tf32r(b4.y); b4.z = tf32r(b4.z); b4.w = tf32r(b4.w);
            *(float4*)&sB[m * GLD + 4 * kq] = b4;
        }
        __syncthreads();

#pragma unroll
        for (int k8 = 0; k8 < 2; k8++) {
            uint32_t a[4][4], b[4][2];
#pragma unroll
            for (int mf = 0; mf < 4; mf++) {
                const float* p = &sA[(64 * wm + 16 * mf + lr) * GLD + k8 * 8 + lc];
                a[mf][0] = fu(p[0]);
                a[mf][1] = fu(p[8 * GLD]);
                a[mf][2] = fu(p[4]);
                a[mf][3] = fu(p[8 * GLD + 4]);
            }
#pragma unroll
            for (int nf = 0; nf < 4; nf++) {
                const float* p = &sB[(32 * wn + 8 * nf + lr) * GLD + k8 * 8 + lc];
                b[nf][0] = fu(p[0]);
                b[nf][1] = fu(p[4]);
            }
#pragma unroll
            for (int mf = 0; mf < 4; mf++)
#pragma unroll
                for (int nf = 0; nf < 4; nf++)
                    mma8(acc[mf][nf], a[mf][0], a[mf][1], a[mf][2], a[mf][3],
                         b[nf][0], b[nf][1]);
        }
        __syncthreads();
    }

#pragma unroll
    for (int mf = 0; mf < 4; mf++) {
        int r0 = bm + 64 * wm + 16 * mf + lr;
#pragma unroll
        for (int nf = 0; nf < 4; nf++) {
            int n = bn + 32 * wn + 8 * nf + 2 * lc;
            float bi0 = bo[n], bi1 = bo[n + 1];
#pragma unroll
            for (int rr = 0; rr < 2; rr++) {
                int r = r0 + 8 * rr;
                float2 v2;
                v2.x = acc[mf][nf][2 * rr + 0] + bi0;
                v2.y = acc[mf][nf][2 * rr + 1] + bi1;
                *(float2*)&out[(size_t)r * D_MODEL + n] = v2;
            }
        }
    }
}

// ---------------------------------------------------------------------------
extern "C" void kernel_launch(void* const* d_in, const int* in_sizes, int n_in,
                              void* d_out, int out_size)
{
    const float* Q    = (const float*)d_in[0];
    const float* K    = (const float*)d_in[1];
    const float* V    = (const float*)d_in[2];
    const int*   mask = (const int*)  d_in[3];
    const float* Wq   = (const float*)d_in[4];
    const float* bq   = (const float*)d_in[5];
    const float* Wk   = (const float*)d_in[6];
    const float* bk   = (const float*)d_in[7];
    const float* Wv   = (const float*)d_in[8];
    const float* bv   = (const float*)d_in[9];
    const float* Wo   = (const float*)d_in[10];
    const float* bo   = (const float*)d_in[11];
    float* out = (float*)d_out;

    cudaFuncSetAttribute(flash_tc3,
                         cudaFuncAttributeMaxDynamicSharedMemorySize, FLASH_SMEM);

    pack_mask<<<(SEQ * (SEQ / 32) * 32) / 256, 256>>>(mask);

    dim3 pg(MROWS / 128, D_MODEL / 128, 3);     // 128 x 4 x 3
    gemm_qkv_tc<<<pg, 256>>>(Q, K, V, Wq, Wk, Wv, bq, bk, bv);

    dim3 ag(SEQ / 128, BH);                     // 16 x 64
    flash_tc3<<<ag, 256, FLASH_SMEM>>>();

    dim3 og(MROWS / 128, D_MODEL / 128);        // 128 x 4
    gemm_out_tc<<<og, 256>>>(Wo, bo, out);
}